// round 17
// baseline (speedup 1.0000x reference)
#include <cuda_runtime.h>
#include <cuda_fp16.h>
#include <cstdint>

// Problem constants
#define B_   16
#define S_   626
#define D_   768
#define H_   12
#define HD_  64
#define M_   (B_*S_)          // 10016
#define BH_  (B_*H_)          // 192
#define SM1_ (S_-1)           // 625
#define PSTR 644              // P row stride (floats); 644%32==4 -> Ph LDSM conflict-free
#define QSH  72               // Qh/Kh/Vh half-tile row stride (halves)
#define QT   32               // q-tile rows in fused_attn (256 threads, 2 blocks/SM)
#define CK   64               // K/V chunk rows in fused_attn
#define AST  24               // proj A tile k-stride (halves)
#define BST  136              // proj B tile n-stride (halves)

// Scratch (device globals; no cudaMalloc allowed)
__device__ __half g_qh[BH_*(size_t)S_*HD_];     // q as half [b,h,s,hd]
__device__ __half g_kh[BH_*(size_t)S_*HD_];     // k as half
__device__ __half g_vh[BH_*(size_t)S_*HD_];     // v as half
__device__ __half g_ctxh[(size_t)M_*D_];        // ctx as half
__device__ __half g_xh[(size_t)M_*D_];          // hidden_states as half
__device__ __half g_wq[D_*D_], g_wk[D_*D_], g_wv[D_*D_], g_wo[D_*D_];
__device__ float  g_contrib[BH_*S_];            // fixed scores col 0

// ---------------------------------------------------------------------------
// helpers
// ---------------------------------------------------------------------------
__device__ __forceinline__ void hmma(float c[4],
    uint32_t a0, uint32_t a1, uint32_t a2, uint32_t a3,
    uint32_t b0, uint32_t b1)
{
    asm volatile(
        "mma.sync.aligned.m16n8k16.row.col.f32.f16.f16.f32 "
        "{%0,%1,%2,%3}, {%4,%5,%6,%7}, {%8,%9}, {%0,%1,%2,%3};"
        : "+f"(c[0]), "+f"(c[1]), "+f"(c[2]), "+f"(c[3])
        : "r"(a0), "r"(a1), "r"(a2), "r"(a3), "r"(b0), "r"(b1));
}

__device__ __forceinline__ void ldsm_x4(
    uint32_t& r0, uint32_t& r1, uint32_t& r2, uint32_t& r3, const void* p)
{
    uint32_t a = (uint32_t)__cvta_generic_to_shared(p);
    asm volatile("ldmatrix.sync.aligned.m8n8.x4.shared.b16 {%0,%1,%2,%3}, [%4];"
        : "=r"(r0), "=r"(r1), "=r"(r2), "=r"(r3) : "r"(a));
}

__device__ __forceinline__ void ldsm_x4_t(
    uint32_t& r0, uint32_t& r1, uint32_t& r2, uint32_t& r3, const void* p)
{
    uint32_t a = (uint32_t)__cvta_generic_to_shared(p);
    asm volatile("ldmatrix.sync.aligned.m8n8.x4.trans.shared.b16 {%0,%1,%2,%3}, [%4];"
        : "=r"(r0), "=r"(r1), "=r"(r2), "=r"(r3) : "r"(a));
}

__device__ __forceinline__ void cp8(void* smem, const void* gmem) {
    uint32_t s = (uint32_t)__cvta_generic_to_shared(smem);
    asm volatile("cp.async.ca.shared.global [%0], [%1], 8;" :: "r"(s), "l"(gmem));
}

__device__ __forceinline__ uint2 pack4h(float4 v) {
    uint2 u;
    __half2 h;
    h = __floats2half2_rn(v.x, v.y); u.x = *(uint32_t*)&h;
    h = __floats2half2_rn(v.z, v.w); u.y = *(uint32_t*)&h;
    return u;
}

__device__ __forceinline__ uint32_t packh2(float a, float b) {
    __half2 h = __floats2half2_rn(a, b);
    return *(uint32_t*)&h;
}

// ---------------------------------------------------------------------------
// f32 -> f16 bulk conversions
// ---------------------------------------------------------------------------
__global__ __launch_bounds__(256) void f2h4(
    const float* __restrict__ src, __half* __restrict__ dst, int n4)
{
    for (int i = blockIdx.x * 256 + threadIdx.x; i < n4; i += gridDim.x * 256) {
        float4 v = ((const float4*)src)[i];
        ((uint2*)dst)[i] = pack4h(v);
    }
}

__global__ __launch_bounds__(256) void f2h4_w(
    const float* __restrict__ w0, const float* __restrict__ w1,
    const float* __restrict__ w2, const float* __restrict__ w3, int n4)
{
    const float* src = (blockIdx.y == 0) ? w0 : (blockIdx.y == 1) ? w1
                     : (blockIdx.y == 2) ? w2 : w3;
    __half* dst = (blockIdx.y == 0) ? g_wq : (blockIdx.y == 1) ? g_wk
                : (blockIdx.y == 2) ? g_wv : g_wo;
    for (int i = blockIdx.x * 256 + threadIdx.x; i < n4; i += gridDim.x * 256) {
        float4 v = ((const float4*)src)[i];
        ((uint2*)dst)[i] = pack4h(v);
    }
}

// ---------------------------------------------------------------------------
// Projection GEMM core (fp16 m16n8k16 + ldmatrix, half gmem operands,
// 1 sync/iter, reg double buffer). Block 128x128, BK=16, warp tile 64x32.
// ---------------------------------------------------------------------------
template <bool QKV>
__device__ __forceinline__ void gemm_core(
    const __half* __restrict__ Asrc, const __half* __restrict__ W,
    const float* __restrict__ bias, float* __restrict__ dstf,
    __half* __restrict__ dsth,
    int m0, int n0,
    __half (*As)[128][AST], __half (*Bs)[16][BST])
{
    const int tid = threadIdx.x;
    const int wid = tid >> 5, lane = tid & 31;
    const int gid = lane >> 2, tk = lane & 3;
    const int wm = (wid & 1) * 64;
    const int wn = (wid >> 1) * 32;
    const int l15 = lane & 15, lhi = (lane >> 4) * 8;

    const int arow = tid >> 1, ak8 = (tid & 1) * 8;
    const int bkr  = tid >> 4, bn8 = (tid & 15) * 8;
    const bool aval = (m0 + arow < M_);

    float acc[4][4][4];
    #pragma unroll
    for (int mi = 0; mi < 4; mi++)
        #pragma unroll
        for (int ni = 0; ni < 4; ni++)
            #pragma unroll
            for (int r = 0; r < 4; r++) acc[mi][ni][r] = 0.f;

    const uint4 z4 = make_uint4(0u, 0u, 0u, 0u);

    {
        uint4 va = z4;
        if (aval) va = *(const uint4*)(Asrc + (size_t)(m0 + arow) * D_ + ak8);
        uint4 vb = *(const uint4*)(W + (size_t)bkr * D_ + n0 + bn8);
        *(uint4*)&As[0][arow][ak8] = va;
        *(uint4*)&Bs[0][bkr][bn8]  = vb;
    }
    __syncthreads();

    const int NK = D_ / 16;   // 48
    for (int kt = 0; kt < NK; kt++) {
        const int cur = kt & 1;
        const bool pf = (kt + 1 < NK);
        uint4 va = z4, vb = z4;
        if (pf) {
            const int k1 = (kt + 1) * 16;
            if (aval) va = *(const uint4*)(Asrc + (size_t)(m0 + arow) * D_ + k1 + ak8);
            vb = *(const uint4*)(W + (size_t)(k1 + bkr) * D_ + n0 + bn8);
        }

        uint32_t af[4][4];
        #pragma unroll
        for (int mi = 0; mi < 4; mi++)
            ldsm_x4(af[mi][0], af[mi][1], af[mi][2], af[mi][3],
                    &As[cur][wm + mi * 16 + l15][lhi]);
        uint32_t bf[8];
        ldsm_x4_t(bf[0], bf[1], bf[2], bf[3], &Bs[cur][l15][wn + lhi]);
        ldsm_x4_t(bf[4], bf[5], bf[6], bf[7], &Bs[cur][l15][wn + 16 + lhi]);

        #pragma unroll
        for (int mi = 0; mi < 4; mi++) {
            hmma(acc[mi][0], af[mi][0], af[mi][1], af[mi][2], af[mi][3], bf[0], bf[1]);
            hmma(acc[mi][1], af[mi][0], af[mi][1], af[mi][2], af[mi][3], bf[2], bf[3]);
            hmma(acc[mi][2], af[mi][0], af[mi][1], af[mi][2], af[mi][3], bf[4], bf[5]);
            hmma(acc[mi][3], af[mi][0], af[mi][1], af[mi][2], af[mi][3], bf[6], bf[7]);
        }

        if (pf) {
            *(uint4*)&As[cur ^ 1][arow][ak8] = va;
            *(uint4*)&Bs[cur ^ 1][bkr][bn8]  = vb;
        }
        __syncthreads();
    }

    #pragma unroll
    for (int mi = 0; mi < 4; mi++) {
        #pragma unroll
        for (int ni = 0; ni < 4; ni++) {
            const int col = n0 + wn + ni * 8 + 2 * tk;
            const float b0v = bias[col], b1v = bias[col + 1];
            const int r0 = m0 + wm + mi * 16 + gid;
            const int r1 = r0 + 8;
            if (QKV) {
                const int h = col >> 6, hd = col & 63;
                if (r0 < M_) {
                    const int b = r0 / S_, s = r0 - b * S_;
                    *(uint32_t*)(dsth + (((size_t)(b * H_ + h)) * S_ + s) * HD_ + hd) =
                        packh2(acc[mi][ni][0] + b0v, acc[mi][ni][1] + b1v);
                }
                if (r1 < M_) {
                    const int b = r1 / S_, s = r1 - b * S_;
                    *(uint32_t*)(dsth + (((size_t)(b * H_ + h)) * S_ + s) * HD_ + hd) =
                        packh2(acc[mi][ni][2] + b0v, acc[mi][ni][3] + b1v);
                }
            } else {
                if (r0 < M_)
                    *(float2*)(dstf + (size_t)r0 * D_ + col) =
                        make_float2(acc[mi][ni][0] + b0v, acc[mi][ni][1] + b1v);
                if (r1 < M_)
                    *(float2*)(dstf + (size_t)r1 * D_ + col) =
                        make_float2(acc[mi][ni][2] + b0v, acc[mi][ni][3] + b1v);
            }
        }
    }
}

__global__ __launch_bounds__(256, 2) void gemm_qkv(
    const float* __restrict__ bq, const float* __restrict__ bk,
    const float* __restrict__ bv)
{
    __shared__ __align__(16) __half As[2][128][AST];
    __shared__ __align__(16) __half Bs[2][16][BST];
    const int m0  = blockIdx.x * 128;
    const int ng  = blockIdx.y * 128;
    const int mat = ng / D_;
    const int n0  = ng - mat * D_;
    const __half* W   = (mat == 0) ? g_wq : (mat == 1) ? g_wk : g_wv;
    const float* bias = (mat == 0) ? bq : (mat == 1) ? bk : bv;
    __half* dsth = (mat == 0) ? g_qh : (mat == 1) ? g_kh : g_vh;
    gemm_core<true>(g_xh, W, bias, nullptr, dsth, m0, n0, As, Bs);
}

__global__ __launch_bounds__(256, 2) void gemm_out(
    const float* __restrict__ bias, float* __restrict__ out)
{
    __shared__ __align__(16) __half As[2][128][AST];
    __shared__ __align__(16) __half Bs[2][16][BST];
    gemm_core<false>(g_ctxh, g_wo, bias, out, nullptr,
                     blockIdx.x * 128, blockIdx.y * 128, As, Bs);
}

// ---------------------------------------------------------------------------
// Fused attention, 32-row q tile, 256 threads, 2 blocks/SM.
//   scores: fp16 LDSM, K chunks (64 rows) double-buffered via cp.async
//   softmax: register-resident, half in-place output
//   ctx:    A via LDSM on Ph; V chunks double-buffered via cp.async
// SMEM: P[32][644] f32 + Qh[32][QSH] + KVh[2][64][QSH]  (~105 KB)
// ---------------------------------------------------------------------------
__global__ __launch_bounds__(256, 2) void fused_attn(
    float* __restrict__ probs, const int* __restrict__ mask)
{
    extern __shared__ float sm[];
    float*  P   = sm;                                   // [QT][PSTR] f32
    __half* Qh  = (__half*)(sm + QT * PSTR);            // [QT][QSH]
    __half* KV0 = Qh + QT * QSH;                        // buf 0: [CK][QSH]
    __half* KV1 = KV0 + CK * QSH;                       // buf 1: [CK][QSH]

    const int bh  = blockIdx.y;
    const int m0  = blockIdx.x * QT;
    const int tid = threadIdx.x;
    const int wid = tid >> 5, lane = tid & 31;
    const int gid = lane >> 2, tk = lane & 3;
    const int wm  = (wid & 1) * 16;      // 2 warps along m (16 rows each) = 32
    const int wns = (wid >> 1) * 16;     // scores: 4 warps x 16 cols = 64
    const int wnc = (wid >> 1) * 16;     // ctx: 4 warps x 16 cols = 64
    const int l15 = lane & 15, lhi = (lane >> 4) * 8;
    const int brow = (lane & 7) + ((lane & 16) ? 8 : 0);
    const int bko  = (lane & 8) ? 8 : 0;
    const int b   = bh / H_;
    const int h   = bh - b * H_;

    const __half* qb = g_qh + (size_t)bh * S_ * HD_;
    const __half* kb = g_kh + (size_t)bh * S_ * HD_;
    const __half* vb = g_vh + (size_t)bh * S_ * HD_;
    float* pgm = probs + (size_t)bh * S_ * S_;

    // per-thread chunk-fill coordinates (4 x 8B per thread = 64x64 halves)
    const int frow[4] = { (tid + 0)  >> 4, (tid + 256) >> 4,
                          (tid + 512) >> 4, (tid + 768) >> 4 };
    const int fc4 = (tid & 15) << 2;

    auto fill_chunk = [&](__half* buf, const __half* src, int base) {
        #pragma unroll
        for (int i = 0; i < 4; i++) {
            const int row = frow[i];
            if (base + row < S_)
                cp8(&buf[row * QSH + fc4], src + (size_t)(base + row) * HD_ + fc4);
            else
                *(uint2*)&buf[row * QSH + fc4] = make_uint2(0u, 0u);
        }
    };

    // prologue: prefetch K chunk 0; load Q tile (regular)
    fill_chunk(KV0, kb, 0);
    asm volatile("cp.async.commit_group;");
    #pragma unroll
    for (int i = 0; i < 2; i++) {
        const int idx = tid + i * 256;
        const int row = idx >> 4, c4 = (idx & 15) << 2;
        uint2 v = make_uint2(0u, 0u);
        if (m0 + row < S_) v = *(const uint2*)(qb + (size_t)(m0 + row) * HD_ + c4);
        *(uint2*)&Qh[row * QSH + c4] = v;
    }
    asm volatile("cp.async.wait_group 0;");
    __syncthreads();

    // ---- scores phase: 10 chunks of 64 key-columns, double-buffered ----
    for (int nc = 0; nc < 10; nc++) {
        __half* cur = (nc & 1) ? KV1 : KV0;
        __half* nxt = (nc & 1) ? KV0 : KV1;
        if (nc + 1 < 10) {
            fill_chunk(nxt, kb, (nc + 1) * CK);
            asm volatile("cp.async.commit_group;");
        }

        const int n0 = nc * CK;
        float acc[2][4];
        #pragma unroll
        for (int ni = 0; ni < 2; ni++)
            #pragma unroll
            for (int r = 0; r < 4; r++) acc[ni][r] = 0.f;

        #pragma unroll
        for (int ks = 0; ks < 64; ks += 16) {
            uint32_t a0, a1, a2, a3;
            ldsm_x4(a0, a1, a2, a3, &Qh[(wm + l15) * QSH + ks + lhi]);
            uint32_t b0, b1, b2, b3;
            ldsm_x4(b0, b1, b2, b3, &cur[(wns + brow) * QSH + ks + bko]);
            hmma(acc[0], a0, a1, a2, a3, b0, b1);
            hmma(acc[1], a0, a1, a2, a3, b2, b3);
        }

        #pragma unroll
        for (int ni = 0; ni < 2; ni++) {
            const int col = n0 + wns + ni * 8 + 2 * tk;   // even
            if (col < S_) {
                *(float2*)&P[(wm + gid    ) * PSTR + col] =
                    make_float2(acc[ni][0] * 0.125f, acc[ni][1] * 0.125f);
                *(float2*)&P[(wm + gid + 8) * PSTR + col] =
                    make_float2(acc[ni][2] * 0.125f, acc[ni][3] * 0.125f);
            }
        }

        asm volatile("cp.async.wait_group 0;");
        __syncthreads();
    }

    // prefetch V chunk 0 (hides behind the whole softmax phase)
    fill_chunk(KV0, vb, 0);
    asm volatile("cp.async.commit_group;");

    // ---- softmax phase: register-resident; warp w owns rows w*4..w*4+3.
    //      Output written as HALF in place (Ph row r = front of f32 row r).
    #define NE 20   // ceil(626/32); covers columns 0..639 for padding
    for (int r = wid * 4; r < wid * 4 + 4; r++) {
        const int q = m0 + r;
        if (q >= S_) break;
        float* row = P + (size_t)r * PSTR;

        float e[NE];
        #pragma unroll
        for (int j = 0; j < NE; j++) {
            const int i = lane + 32 * j;
            e[j] = (i < S_) ? row[i] : -3.4e38f;
        }

        float mx = -3.4e38f;
        #pragma unroll
        for (int j = 0; j < NE; j++) mx = fmaxf(mx, e[j]);
        #pragma unroll
        for (int o = 16; o; o >>= 1) mx = fmaxf(mx, __shfl_xor_sync(0xffffffffu, mx, o));

        if (q == 0) {
            const float add = mx * 0.25f;
            #pragma unroll
            for (int j = 0; j < NE; j++) {
                const int i = lane + 32 * j;
                if (i < S_) {
                    const int mk = (i == 0) ? 0 : mask[b * SM1_ + i - 1];
                    if (mk == 0) e[j] += add;
                }
            }
            mx = -3.4e38f;
            #pragma unroll
            for (int j = 0; j < NE; j++) mx = fmaxf(mx, e[j]);
            #pragma unroll
            for (int o = 16; o; o >>= 1) mx = fmaxf(mx, __shfl_xor_sync(0xffffffffu, mx, o));
        }

        if (lane == 0) g_contrib[(size_t)bh * S_ + q] = e[0];   // fixed score at k=0

        float s = 0.f;
        #pragma unroll
        for (int j = 0; j < NE; j++) {
            const int i = lane + 32 * j;
            const float v = (i < S_) ? __expf(e[j] - mx) : 0.f;
            e[j] = v;
            s += v;
        }
        #pragma unroll
        for (int o = 16; o; o >>= 1) s += __shfl_xor_sync(0xffffffffu, s, o);
        const float inv = 1.0f / s;

        // ensure all f32 reads of this row precede the aliasing half writes
        asm volatile("" ::: "memory");

        __half* ph = (__half*)row;                    // overlays this row only
        float* prow = pgm + (size_t)q * S_;
        #pragma unroll
        for (int j = 0; j < NE; j++) {
            const int i = lane + 32 * j;
            if (i < S_) {
                const float p = e[j] * inv;
                ph[i] = __float2half_rn(p);
                prow[i] = p;
            } else {
                ph[i] = __float2half_rn(0.f * inv);   // pad cols 626..639
            }
        }
    }
    #undef NE
    asm volatile("cp.async.wait_group 0;");
    __syncthreads();

    // ---- ctx phase: 10 chunks of 64 k-rows, double-buffered ----
    float cacc[2][4];
    #pragma unroll
    for (int ni = 0; ni < 2; ni++)
        #pragma unroll
        for (int r = 0; r < 4; r++) cacc[ni][r] = 0.f;

    const __half* Ph = (const __half*)P;              // row stride 2*PSTR halves

    for (int kc = 0; kc < 10; kc++) {
        __half* cur = (kc & 1) ? KV1 : KV0;
        __half* nxt = (kc & 1) ? KV0 : KV1;
        if (kc + 1 < 10) {
            fill_chunk(nxt, vb, (kc + 1) * CK);
            asm volatile("cp.async.commit_group;");
        }

        const int k0 = kc * CK;
        #pragma unroll
        for (int ks = 0; ks < 64; ks += 16) {
            uint32_t a0, a1, a2, a3;
            ldsm_x4(a0, a1, a2, a3,
                    &Ph[(size_t)(wm + l15) * (2 * PSTR) + k0 + ks + lhi]);
            uint32_t b0, b1, b2, b3;
            ldsm_x4_t(b0, b1, b2, b3, &cur[(ks + l15) * QSH + wnc + lhi]);
            hmma(cacc[0], a0, a1, a2, a3, b0, b1);
            hmma(cacc[1], a0, a1, a2, a3, b2, b3);
        }

        if (kc + 1 < 10) {
            asm volatile("cp.async.wait_group 0;");
            __syncthreads();
        }
    }

    // ctx epilogue -> half (gemm_out reads half A)
    #pragma unroll
    for (int ni = 0; ni < 2; ni++) {
        const int col = wnc + ni * 8 + 2 * tk;   // even, 0..62
        const int r0 = m0 + wm + gid;
        const int r1 = r0 + 8;
        if (r0 < S_)
            *(uint32_t*)(g_ctxh + ((size_t)(b * S_ + r0)) * D_ + h * HD_ + col) =
                packh2(cacc[ni][0], cacc[ni][1]);
        if (r1 < S_)
            *(uint32_t*)(g_ctxh + ((size_t)(b * S_ + r1)) * D_ + h * HD_ + col) =
                packh2(cacc[ni][2], cacc[ni][3]);
    }
}

// ---------------------------------------------------------------------------
// Contribution: softmax over q of g_contrib[bh, :]
// ---------------------------------------------------------------------------
__global__ __launch_bounds__(256) void contrib_kernel(float* __restrict__ out)
{
    const int bh = blockIdx.x;
    const float* src = g_contrib + (size_t)bh * S_;
    __shared__ float red[8];
    const int tid = threadIdx.x;

    float m = -3.4e38f;
    for (int i = tid; i < S_; i += 256) m = fmaxf(m, src[i]);
    #pragma unroll
    for (int o = 16; o; o >>= 1) m = fmaxf(m, __shfl_xor_sync(0xffffffffu, m, o));
    if ((tid & 31) == 0) red[tid >> 5] = m;
    __syncthreads();
    if (tid == 0) {
        float mm = red[0];
        #pragma unroll
        for (int w = 1; w < 8; w++) mm = fmaxf(mm, red[w]);
        red[0] = mm;
    }
    __syncthreads();
    m = red[0];
    __syncthreads();

    float s = 0.f;
    for (int i = tid; i < S_; i += 256) s += expf(src[i] - m);
    #pragma unroll
    for (int o = 16; o; o >>= 1) s += __shfl_xor_sync(0xffffffffu, s, o);
    if ((tid & 31) == 0) red[tid >> 5] = s;
    __syncthreads();
    if (tid == 0) {
        float ss = 0.f;
        #pragma unroll
        for (int w = 0; w < 8; w++) ss += red[w];
        red[0] = ss;
    }
    __syncthreads();
    const float inv = 1.0f / red[0];
    for (int i = tid; i < S_; i += 256)
        out[(size_t)bh * S_ + i] = expf(src[i] - m) * inv;
}

// ---------------------------------------------------------------------------
// Launch
// ---------------------------------------------------------------------------
extern "C" void kernel_launch(void* const* d_in, const int* in_sizes, int n_in,
                              void* d_out, int out_size)
{
    const float* hs = (const float*)d_in[0];
    const int*  mask = (const int*) d_in[1];
    const float* Wq = (const float*)d_in[2];
    const float* bq = (const float*)d_in[3];
    const float* Wk = (const float*)d_in[4];
    const float* bk = (const float*)d_in[5];
    const float* Wv = (const float*)d_in[6];
    const float* bv = (const float*)d_in[7];
    const float* Wo = (const float*)d_in[8];
    const float* bo = (const float*)d_in[9];

    float* out     = (float*)d_out;
    float* att_out = out;                                       // [B,S,D]
    float* probs   = out + (size_t)M_ * D_;                     // [B,H,S,S]
    float* contrib = probs + (size_t)BH_ * S_ * S_;             // [B,H,S]

    // SMEM: P f32 + Qh half + KVh half x2 buffers (64 rows each)
    const int smem_bytes = QT * PSTR * 4 + QT * QSH * 2 + 2 * CK * QSH * 2;
    cudaFuncSetAttribute(fused_attn,
        cudaFuncAttributeMaxDynamicSharedMemorySize, smem_bytes);

    __half* xh;
    cudaGetSymbolAddress((void**)&xh, g_xh);

    const int nx4 = (M_ * D_) / 4;
    const int nw4 = (D_ * D_) / 4;
    f2h4<<<(nx4 + 255) / 256, 256>>>(hs, xh, nx4);
    f2h4_w<<<dim3(144, 4), 256>>>(Wq, Wk, Wv, Wo, nw4);

    gemm_qkv<<<dim3(79, 18), 256>>>(bq, bk, bv);
    fused_attn<<<dim3(20, 192), 256, smem_bytes>>>(probs, mask);
    contrib_kernel<<<BH_, 256>>>(contrib);
    gemm_out<<<dim3(79, 6), 256>>>(bo, att_out);
}